// round 16
// baseline (speedup 1.0000x reference)
#include <cuda_runtime.h>
#include <cuda_fp16.h>
#include <math.h>
#include <stdint.h>

// Problem constants: B=8, n=1024, dQ=dV=512, H=8, d=64, HB=64
#define NSEQ   1024
#define DHEAD  64
#define DVTOT  512
#define NBATCH 8
#define NHB    64

#define SSCALE 0.044194173824159216f   // 1/sqrt(512)
#define LOG2E  1.4426950408889634f
#define SS2    (SSCALE * LOG2E)        // exp(s*SSCALE) = ex2(s*SS2)
#define LOGMU  (-6.9314615657f)        // log(1/1024 + 1e-8)
#define MUVAL  (0.0009765725f)         // 1/1024 + 1e-8

// Scratch (device globals; no allocation allowed)
__device__ float  g_Qh  [NHB * NSEQ * DHEAD];   // head-major Q_ fp32 (residual)
__device__ __half g_Qh16[NHB * NSEQ * DHEAD];   // head-major Q_ fp16 (mma operand)
__device__ __half g_Qh16s[NHB * NSEQ * DHEAD];  // Q_ * SS2 fp16 (S-pass A operand)
__device__ __half g_Qv16[NHB * NSEQ * DHEAD];   // e^{v_j} * Q_j fp16 (AV V operand)
__device__ float  g_Oh [NBATCH * NSEQ * DVTOT]; // O_ in merged (b,i,512) layout
__device__ float  g_X  [NBATCH * NSEQ * DVTOT];
__device__ __half g_X16[NBATCH * NSEQ * DVTOT];
__device__ float  g_T  [NBATCH * NSEQ * DVTOT];
__device__ __half g_A16[NBATCH * NSEQ * DVTOT]; // fp16 Q input
__device__ __half g_W16q[DVTOT * DVTOT];
__device__ __half g_W16o[DVTOT * DVTOT];
// partial sums: g_part (pass 0, row/col sums of P) ; g_part2 (pass 1, for v)
__device__ float  g_part [NHB * 8 * NSEQ];
__device__ float  g_part2[NHB * 8 * NSEQ];

// ---------------------------------------------------------------------------
// helpers
// ---------------------------------------------------------------------------
__device__ __forceinline__ void mma16h(float* c, const unsigned* a, const unsigned* b) {
    asm volatile(
        "mma.sync.aligned.m16n8k16.row.col.f32.f16.f16.f32 "
        "{%0,%1,%2,%3},{%4,%5,%6,%7},{%8,%9},{%0,%1,%2,%3};\n"
        : "+f"(c[0]), "+f"(c[1]), "+f"(c[2]), "+f"(c[3])
        : "r"(a[0]), "r"(a[1]), "r"(a[2]), "r"(a[3]), "r"(b[0]), "r"(b[1]));
}
__device__ __forceinline__ unsigned smaddr(const void* p) {
    return (unsigned)__cvta_generic_to_shared(p);
}
__device__ __forceinline__ void ldm_x4(unsigned* r, unsigned a) {
    asm volatile("ldmatrix.sync.aligned.m8n8.x4.shared.b16 {%0,%1,%2,%3},[%4];"
                 : "=r"(r[0]), "=r"(r[1]), "=r"(r[2]), "=r"(r[3]) : "r"(a));
}
__device__ __forceinline__ void ldm_x4t(unsigned* r, unsigned a) {
    asm volatile("ldmatrix.sync.aligned.m8n8.x4.trans.shared.b16 {%0,%1,%2,%3},[%4];"
                 : "=r"(r[0]), "=r"(r[1]), "=r"(r[2]), "=r"(r[3]) : "r"(a));
}
__device__ __forceinline__ unsigned fh2(float a, float b) {
    __half2 h = __floats2half2_rn(a, b);
    return *(unsigned*)&h;
}
__device__ __forceinline__ float ex2(float x) {
    float r;
    asm("ex2.approx.ftz.f32 %0, %1;" : "=f"(r) : "f"(x));
    return r;
}
__device__ __forceinline__ unsigned h2ex2(unsigned x) {
    unsigned r;
    asm("ex2.approx.f16x2 %0, %1;" : "=r"(r) : "r"(x));
    return r;
}
__device__ __forceinline__ void cpa16(unsigned s, const void* g) {
    asm volatile("cp.async.ca.shared.global [%0], [%1], 16;" :: "r"(s), "l"(g) : "memory");
}
__device__ __forceinline__ void cpa_commit() {
    asm volatile("cp.async.commit_group;" ::: "memory");
}
template <int N>
__device__ __forceinline__ void cpa_wait() {
    asm volatile("cp.async.wait_group %0;" :: "n"(N) : "memory");
}

// ---------------------------------------------------------------------------
// fp32 -> fp16 conversion for GEMM operands (Q, Wq, Wo). One launch.
// ---------------------------------------------------------------------------
__global__ void __launch_bounds__(256) cvt_kernel(const float* __restrict__ Q,
                                                  const float* __restrict__ Wq,
                                                  const float* __restrict__ Wo) {
    size_t t = ((size_t)blockIdx.x * 256 + threadIdx.x) * 8;
    const float* src;
    __half* dst;
    size_t off;
    if (t < 4194304) { src = Q;  dst = g_A16;  off = t; }
    else if (t < 4456448) { src = Wq; dst = g_W16q; off = t - 4194304; }
    else { src = Wo; dst = g_W16o; off = t - 4456448; }
    float4 a = *(const float4*)(src + off);
    float4 b = *(const float4*)(src + off + 4);
    uint4 p;
    p.x = fh2(a.x, a.y); p.y = fh2(a.z, a.w);
    p.z = fh2(b.x, b.y); p.w = fh2(b.z, b.w);
    *(uint4*)(dst + off) = p;
}

// ---------------------------------------------------------------------------
// Symmetric-tile LSE pass (R14 config). 3 CTAs/SM. A from prescaled copy.
// MODE 0: partials of rowsum/colsum of P -> g_part
// MODE 1: e^u from g_part; weighted partials for v -> g_part2
// ---------------------------------------------------------------------------
template <int MODE>
__global__ void __launch_bounds__(256, 3) sym_lse() {
    __shared__ __align__(16) __half Qi[128 * 72];
    __shared__ __align__(16) __half Qj[128 * 72];
    __shared__ float csh[4][128];
    __shared__ float ps[256];
    __shared__ float eua[128], eub[128];

    const int bh = blockIdx.y;
    int a = 0, tt = blockIdx.x;
    while (tt >= 8 - a) { tt -= 8 - a; a++; }
    const int b = a + tt;

    const int tid = threadIdx.x, lane = tid & 31, w = tid >> 5;
    const int mw = w & 3, w2 = w >> 2;
    const int wm = mw * 32, wn = w2 * 64;
    const __half* Qb  = g_Qh16  + (size_t)bh * (NSEQ * DHEAD);
    const __half* Qbs = g_Qh16s + (size_t)bh * (NSEQ * DHEAD);

#pragma unroll
    for (int r = 0; r < 4; r++) {
        int idx = tid + r * 256;
        int row = idx >> 3, q = (idx & 7) * 8;
        cpa16(smaddr(Qi + row * 72 + q), Qbs + (size_t)(a * 128 + row) * DHEAD + q);
        cpa16(smaddr(Qj + row * 72 + q), Qb  + (size_t)(b * 128 + row) * DHEAD + q);
    }
    if (MODE == 1 && tid < 128) {
        float sa_ = 0.f, sb_ = 0.f;
#pragma unroll
        for (int k = 0; k < 8; k++) {
            sa_ += g_part[((size_t)bh * 8 + k) * NSEQ + a * 128 + tid];
            sb_ += g_part[((size_t)bh * 8 + k) * NSEQ + b * 128 + tid];
        }
        eua[tid] = MUVAL / sa_;
        eub[tid] = MUVAL / sb_;
    }
    cpa_commit();
    cpa_wait<0>();
    __syncthreads();

    float eu4[2][2];
    if (MODE == 1) {
#pragma unroll
        for (int mt = 0; mt < 2; mt++)
#pragma unroll
            for (int h = 0; h < 2; h++)
                eu4[mt][h] = eua[wm + mt * 16 + (lane >> 2) + h * 8];
    }

    float ls[2][2] = {{0.f, 0.f}, {0.f, 0.f}};

#pragma unroll
    for (int nh = 0; nh < 2; nh++) {
        const int wnh = wn + nh * 32;

        float sa[2][4][4];
#pragma unroll
        for (int x = 0; x < 2; x++)
#pragma unroll
            for (int y = 0; y < 4; y++)
#pragma unroll
                for (int z = 0; z < 4; z++) sa[x][y][z] = 0.f;

#pragma unroll
        for (int kk = 0; kk < 4; kk++) {
            unsigned af0[4], af1[4];
            {
                int col = kk * 16 + (lane >> 4) * 8;
                ldm_x4(af0, smaddr(Qi + (wm + (lane & 15)) * 72 + col));
                ldm_x4(af1, smaddr(Qi + (wm + 16 + (lane & 15)) * 72 + col));
            }
#pragma unroll
            for (int nb = 0; nb < 2; nb++) {
                unsigned bq[4];
                ldm_x4(bq, smaddr(Qj + (wnh + nb * 16 + ((lane >> 4) & 1) * 8 + (lane & 7)) * 72 +
                                  kk * 16 + ((lane >> 3) & 1) * 8));
                mma16h(sa[0][2 * nb], af0, bq);
                mma16h(sa[1][2 * nb], af1, bq);
                mma16h(sa[0][2 * nb + 1], af0, bq + 2);
                mma16h(sa[1][2 * nb + 1], af1, bq + 2);
            }
        }

        float cp[4][2];
#pragma unroll
        for (int nt = 0; nt < 4; nt++) { cp[nt][0] = 0.f; cp[nt][1] = 0.f; }

#pragma unroll
        for (int mt = 0; mt < 2; mt++)
#pragma unroll
            for (int nt = 0; nt < 4; nt++) {
                int colb = wnh + nt * 8 + 2 * (lane & 3);
#pragma unroll
                for (int rg = 0; rg < 4; rg++) {
                    float e = ex2(sa[mt][nt][rg]);   // SS2 baked into A copy
                    int h = rg >> 1, d = rg & 1;
                    if (MODE == 0) {
                        ls[mt][h] += e;
                        cp[nt][d] += e;
                    } else {
                        ls[mt][h] += eub[colb + d] * e;
                        cp[nt][d] += eu4[mt][h] * e;
                    }
                }
            }

#pragma unroll
        for (int nt = 0; nt < 4; nt++)
#pragma unroll
            for (int d = 0; d < 2; d++) {
                float v = cp[nt][d];
                v += __shfl_xor_sync(0xffffffffu, v, 4);
                v += __shfl_xor_sync(0xffffffffu, v, 8);
                v += __shfl_xor_sync(0xffffffffu, v, 16);
                cp[nt][d] = v;
            }
        if (lane < 4) {
#pragma unroll
            for (int nt = 0; nt < 4; nt++) {
                csh[mw][wnh + nt * 8 + 2 * lane + 0] = cp[nt][0];
                csh[mw][wnh + nt * 8 + 2 * lane + 1] = cp[nt][1];
            }
        }
    }

#pragma unroll
    for (int mt = 0; mt < 2; mt++)
#pragma unroll
        for (int h = 0; h < 2; h++) {
            float v = ls[mt][h];
            v += __shfl_xor_sync(0xffffffffu, v, 1);
            v += __shfl_xor_sync(0xffffffffu, v, 2);
            if ((lane & 3) == 0)
                ps[w2 * 128 + wm + mt * 16 + (lane >> 2) + h * 8] = v;
        }
    __syncthreads();

    float* dst = (MODE == 0) ? g_part : g_part2;
    if (tid < 128) {
        if (MODE == 0 || a != b) {
            float rs = ps[tid] + ps[128 + tid];
            dst[((size_t)bh * 8 + b) * NSEQ + a * 128 + tid] = rs;
        }
        if (MODE == 1 || a != b) {
            float cs = csh[0][tid] + csh[1][tid] + csh[2][tid] + csh[3][tid];
            dst[((size_t)bh * 8 + a) * NSEQ + b * 128 + tid] = cs;
        }
    }
}

// ---------------------------------------------------------------------------
// qv: compute v from g_part2 and emit g_Qv16 = e^{v} * Q (fp16).
// 256 thr x 8 halves = 32 rows per block; ev computed once per row in smem.
// ---------------------------------------------------------------------------
__global__ void __launch_bounds__(256) qv_kernel() {
    __shared__ float ev[32];
    const int tid = threadIdx.x;
    const int g0 = blockIdx.x * 32;
    if (tid < 32) {
        int g = g0 + tid;
        int bh = g >> 10, pos = g & 1023;
        float s = 0.f;
#pragma unroll
        for (int k = 0; k < 8; k++)
            s += g_part2[((size_t)bh * 8 + k) * NSEQ + pos];
        ev[tid] = ex2((LOGMU - __logf(s)) * LOG2E);   // e^{v}
    }
    __syncthreads();
    int row = g0 + (tid >> 3);
    int q = (tid & 7) * 8;
    float e = ev[tid >> 3];
    uint4 src = *(const uint4*)(g_Qh16 + (size_t)row * DHEAD + q);
    __half2 h0 = *(__half2*)&src.x, h1 = *(__half2*)&src.y;
    __half2 h2v = *(__half2*)&src.z, h3 = *(__half2*)&src.w;
    uint4 dst;
    dst.x = fh2(__low2float(h0) * e, __high2float(h0) * e);
    dst.y = fh2(__low2float(h1) * e, __high2float(h1) * e);
    dst.z = fh2(__low2float(h2v) * e, __high2float(h2v) * e);
    dst.w = fh2(__low2float(h3) * e, __high2float(h3) * e);
    *(uint4*)(g_Qv16 + (size_t)row * DHEAD + q) = dst;
}

// ---------------------------------------------------------------------------
// Pass C: O_ = Q_ + e^{u_i} * (P @ Qv), Qv = e^{v} Q pre-scaled, P = 2^{sa}.
// ak = ex2(pack(sa)) only; row scale su = 1024 e^{u} applied at epilogue.
// 8 warps x 16 rows; two 64-col halves; hoisted af; 2 CTAs/SM.
// ---------------------------------------------------------------------------
__global__ void __launch_bounds__(256, 2) sink_av_kernel() {
    extern __shared__ __align__(16) char smraw[];
    __half* Qi = (__half*)smraw;                 // 128*72 (scaled copy)
    __half* QjA = Qi + 9216;                     // Qj buf 0
    __half* QjB = QjA + 9216;                    // Qj buf 1
    __half* QvA = QjB + 9216;                    // Qv buf 0
    __half* QvB = QvA + 9216;                    // Qv buf 1

    const int bh = blockIdx.y;
    const int i0 = blockIdx.x * 128;
    const int tid = threadIdx.x, lane = tid & 31, w = tid >> 5;
    const int wm = w * 16;
    const __half* Qb  = g_Qh16  + (size_t)bh * (NSEQ * DHEAD);
    const __half* Qbs = g_Qh16s + (size_t)bh * (NSEQ * DHEAD);
    const __half* Qv  = g_Qv16  + (size_t)bh * (NSEQ * DHEAD);
    const float* Qf32 = g_Qh + (size_t)bh * (NSEQ * DHEAD);
    __half* Qjb[2] = { QjA, QjB };
    __half* Qvb[2] = { QvA, QvB };
    const int bb = bh & 7, hh2 = bh >> 3;        // batch, head

#pragma unroll
    for (int r = 0; r < 4; r++) {
        int idx = tid + r * 256;
        int row = idx >> 3, q = (idx & 7) * 8;
        cpa16(smaddr(Qi + row * 72 + q), Qbs + (size_t)(i0 + row) * DHEAD + q);
        cpa16(smaddr(QjA + row * 72 + q), Qb + (size_t)row * DHEAD + q);
        cpa16(smaddr(QvA + row * 72 + q), Qv + (size_t)row * DHEAD + q);
    }
    cpa_commit();

    float r0s = 0.f, r1s = 0.f;
#pragma unroll
    for (int k = 0; k < 8; k++) {
        r0s += g_part[((size_t)bh * 8 + k) * NSEQ + i0 + wm + (lane >> 2)];
        r1s += g_part[((size_t)bh * 8 + k) * NSEQ + i0 + wm + (lane >> 2) + 8];
    }
    // su = 1024 * e^{u} (row scales applied at epilogue)
    const float su0 = ex2((LOGMU - __logf(r0s)) * LOG2E + 10.f);
    const float su1 = ex2((LOGMU - __logf(r1s)) * LOG2E + 10.f);
    cpa_wait<0>();
    __syncthreads();

    unsigned af[4][4];
#pragma unroll
    for (int kk = 0; kk < 4; kk++)
        ldm_x4(af[kk], smaddr(Qi + (wm + (lane & 15)) * 72 + kk * 16 + (lane >> 4) * 8));

    float oa[8][4];
#pragma unroll
    for (int y = 0; y < 8; y++)
#pragma unroll
        for (int z = 0; z < 4; z++) oa[y][z] = 0.f;

    for (int jt = 0; jt < 8; jt++) {
        __syncthreads();
        if (jt < 7) {
            int j0 = (jt + 1) * 128, buf = (jt + 1) & 1;
#pragma unroll
            for (int r = 0; r < 4; r++) {
                int idx = tid + r * 256;
                int row = idx >> 3, q = (idx & 7) * 8;
                cpa16(smaddr(Qjb[buf] + row * 72 + q), Qb + (size_t)(j0 + row) * DHEAD + q);
                cpa16(smaddr(Qvb[buf] + row * 72 + q), Qv + (size_t)(j0 + row) * DHEAD + q);
            }
            cpa_commit();
            cpa_wait<1>();
        } else {
            cpa_wait<0>();
        }
        __syncthreads();

        const __half* Qc = Qjb[jt & 1];
        const __half* Vc = Qvb[jt & 1];

#pragma unroll
        for (int h = 0; h < 2; h++) {
            const int jb = h * 64;
            float sa[8][4];
#pragma unroll
            for (int y = 0; y < 8; y++)
#pragma unroll
                for (int z = 0; z < 4; z++) sa[y][z] = 0.f;

#pragma unroll
            for (int kk = 0; kk < 4; kk++) {
#pragma unroll
                for (int nb = 0; nb < 4; nb++) {
                    unsigned bq[4];
                    ldm_x4(bq, smaddr(Qc + (jb + nb * 16 + ((lane >> 4) & 1) * 8 + (lane & 7)) * 72 +
                                      kk * 16 + ((lane >> 3) & 1) * 8));
                    mma16h(sa[2 * nb], af[kk], bq);
                    mma16h(sa[2 * nb + 1], af[kk], bq + 2);
                }
            }

            // ak = 2^{sa} packed fp16 (u/v scales moved out of the tile)
            unsigned ak[4][4];
#pragma unroll
            for (int s2 = 0; s2 < 4; s2++) {
                const float* s0 = sa[2 * s2];
                const float* s1 = sa[2 * s2 + 1];
                ak[s2][0] = h2ex2(fh2(s0[0], s0[1]));
                ak[s2][1] = h2ex2(fh2(s0[2], s0[3]));
                ak[s2][2] = h2ex2(fh2(s1[0], s1[1]));
                ak[s2][3] = h2ex2(fh2(s1[2], s1[3]));
            }

            // O += P @ Qv (K = these 64 j)
#pragma unroll
            for (int s2 = 0; s2 < 4; s2++) {
#pragma unroll
                for (int nb = 0; nb < 4; nb++) {
                    unsigned bq[4];
                    ldm_x4t(bq, smaddr(Vc + (jb + s2 * 16 + (lane & 15)) * 72 +
                                       nb * 16 + ((lane >> 4) & 1) * 8));
                    mma16h(oa[2 * nb], ak[s2], bq);
                    mma16h(oa[2 * nb + 1], ak[s2], bq + 2);
                }
            }
        }
    }

    // epilogue: O_ = Q_ + su * oa, merged (b,i,512) layout, float2 vectorized
#pragma unroll
    for (int nt = 0; nt < 8; nt++) {
        int ri = i0 + wm + (lane >> 2);
        int col = nt * 8 + 2 * (lane & 3);
        int gcol = hh2 * 64 + col;
        float2 q0 = *(const float2*)(Qf32 + (size_t)ri * DHEAD + col);
        float2 o0 = { su0 * oa[nt][0] + q0.x, su0 * oa[nt][1] + q0.y };
        *(float2*)(g_Oh + ((size_t)(bb * NSEQ + ri) * DVTOT) + gcol) = o0;
        int ri8 = ri + 8;
        float2 q1 = *(const float2*)(Qf32 + (size_t)ri8 * DHEAD + col);
        float2 o1 = { su1 * oa[nt][2] + q1.x, su1 * oa[nt][3] + q1.y };
        *(float2*)(g_Oh + ((size_t)(bb * NSEQ + ri8) * DVTOT) + gcol) = o1;
    }
}

// ---------------------------------------------------------------------------
// fp16 GEMM (BM=128 BN=128 BK=64, 2 CTAs/SM, grid 4x64)
// MODE 0: scatter head-major into g_Qh + g_Qh16 + g_Qh16s (scaled)
// MODE 1: A = g_X16; g_T = g_X + relu(C + bias)
// ---------------------------------------------------------------------------
template <int MODE>
__global__ void __launch_bounds__(256, 2) gemm512h(const float* __restrict__ bias) {
    __shared__ __align__(16) __half As[2][128 * 72];
    __shared__ __align__(16) __half Bs[2][128 * 72];
    const __half* A16 = MODE ? g_X16 : g_A16;
    const __half* W16 = MODE ? g_W16o : g_W16q;

    const int m0 = blockIdx.y * 128, n0 = blockIdx.x * 128;
    const int tid = threadIdx.x, lane = tid & 31, w = tid >> 5;
    const int wm = (w & 3) * 32, wn = (w >> 2) * 64;

    float acc[2][8][4];
#pragma unroll
    for (int x = 0; x < 2; x++)
#pragma unroll
        for (int y = 0; y < 8; y++)
#pragma unroll
            for (int z = 0; z < 4; z++) acc[x][y][z] = 0.f;

#pragma unroll
    for (int c = 0; c < 4; c++) {
        int idx = tid + c * 256;
        int row = idx >> 3, ch = (idx & 7) * 8;
        cpa16(smaddr(&As[0][row * 72 + ch]), A16 + (size_t)(m0 + row) * 512 + ch);
        cpa16(smaddr(&Bs[0][row * 72 + ch]), W16 + (size_t)(n0 + row) * 512 + ch);
    }
    cpa_commit();

    for (int kt = 0; kt < 8; kt++) {
        __syncthreads();
        if (kt < 7) {
            int s = (kt + 1) & 1, k0 = (kt + 1) * 64;
#pragma unroll
            for (int c = 0; c < 4; c++) {
                int idx = tid + c * 256;
                int row = idx >> 3, ch = (idx & 7) * 8;
                cpa16(smaddr(&As[s][row * 72 + ch]), A16 + (size_t)(m0 + row) * 512 + k0 + ch);
                cpa16(smaddr(&Bs[s][row * 72 + ch]), W16 + (size_t)(n0 + row) * 512 + k0 + ch);
            }
            cpa_commit();
            cpa_wait<1>();
        } else {
            cpa_wait<0>();
        }
        __syncthreads();

        const __half* as = As[kt & 1];
        const __half* bs = Bs[kt & 1];
#pragma unroll
        for (int kk = 0; kk < 4; kk++) {
            unsigned af[2][4];
#pragma unroll
            for (int mt = 0; mt < 2; mt++)
                ldm_x4(af[mt], smaddr(as + (wm + mt * 16 + (lane & 15)) * 72 +
                                      kk * 16 + (lane >> 4) * 8));
#pragma unroll
            for (int nb = 0; nb < 4; nb++) {
                unsigned bq[4];
                ldm_x4(bq, smaddr(bs + (wn + nb * 16 + ((lane >> 4) & 1) * 8 + (lane & 7)) * 72 +
                                  kk * 16 + ((lane >> 3) & 1) * 8));
                mma16h(acc[0][2 * nb], af[0], bq);
                mma16h(acc[1][2 * nb], af[1], bq);
                mma16h(acc[0][2 * nb + 1], af[0], bq + 2);
                mma16h(acc[1][2 * nb + 1], af[1], bq + 2);
            }
        }
    }

#pragma unroll
    for (int mt = 0; mt < 2; mt++)
#pragma unroll
        for (int nt = 0; nt < 8; nt++) {
            int row = m0 + wm + mt * 16 + (lane >> 2);
            int col = n0 + wn + nt * 8 + 2 * (lane & 3);
            float b0 = bias[col], b1 = bias[col + 1];
#pragma unroll
            for (int hh = 0; hh < 2; hh++) {
                int rr = row + hh * 8;
                float v0 = acc[mt][nt][2 * hh] + b0;
                float v1 = acc[mt][nt][2 * hh + 1] + b1;
                if (MODE == 0) {
                    int b = rr >> 10, i = rr & 1023;
                    int h = col >> 6, dc = col & 63;
                    size_t idx = ((size_t)((h << 3) + b) * NSEQ + i) * DHEAD + dc;
                    *(float2*)(g_Qh + idx) = make_float2(v0, v1);
                    *(unsigned*)((__half*)g_Qh16 + idx) = fh2(v0, v1);
                    *(unsigned*)((__half*)g_Qh16s + idx) = fh2(v0 * SS2, v1 * SS2);
                } else {
                    float2 x = *(const float2*)(g_X + (size_t)rr * 512 + col);
                    float2 t = { fmaxf(v0, 0.f) + x.x, fmaxf(v1, 0.f) + x.y };
                    *(float2*)(g_T + (size_t)rr * 512 + col) = t;
                }
            }
        }
}

// ---------------------------------------------------------------------------
// LayerNorm, vectorized: 128 threads x float4, one row per block.
// ---------------------------------------------------------------------------
__global__ void __launch_bounds__(128) ln_kernel(const float* __restrict__ gg,
                                                 const float* __restrict__ bb,
                                                 float* __restrict__ out, int mode) {
    const int m = blockIdx.x, t = threadIdx.x;
    const float* src = (mode == 0) ? g_Oh : g_T;
    float4 v = *(const float4*)(src + (size_t)m * 512 + t * 4);
    float s = v.x + v.y + v.z + v.w;
    float q = v.x * v.x + v.y * v.y + v.z * v.z + v.w * v.w;
#pragma unroll
    for (int off = 16; off; off >>= 1) {
        s += __shfl_xor_sync(0xffffffffu, s, off);
        q += __shfl_xor_sync(0xffffffffu, q, off);
    }
    __shared__ float ss[4], sq[4];
    int wr = t >> 5, lane = t & 31;
    if (!lane) { ss[wr] = s; sq[wr] = q; }
    __syncthreads();
    float S = ss[0] + ss[1] + ss[2] + ss[3];
    float Q2 = sq[0] + sq[1] + sq[2] + sq[3];
    float mean = S * (1.f / 512.f);
    float var = Q2 * (1.f / 512.f) - mean * mean;
    float rstd = rsqrtf(var + 1e-5f);
    float4 G = *(const float4*)(gg + t * 4);
    float4 Bv = *(const float4*)(bb + t * 4);
    float4 y;
    y.x = (v.x - mean) * rstd * G.x + Bv.x;
    y.y = (v.y - mean) * rstd * G.y + Bv.y;
    y.z = (v.z - mean) * rstd * G.z + Bv.z;
    y.w = (v.w - mean) * rstd * G.w + Bv.w;
    if (mode == 0) {
        *(float4*)(g_X + (size_t)m * 512 + t * 4) = y;
        uint2 hp;
        hp.x = fh2(y.x, y.y);
        hp.y = fh2(y.z, y.w);
        *(uint2*)(g_X16 + (size_t)m * 512 + t * 4) = hp;
    } else {
        *(float4*)(out + (size_t)m * 512 + t * 4) = y;
    }
}

// ---------------------------------------------------------------------------
extern "C" void kernel_launch(void* const* d_in, const int* in_sizes, int n_in,
                              void* d_out, int out_size) {
    (void)in_sizes; (void)n_in; (void)out_size;
    const float* Q  = (const float*)d_in[0];
    // d_in[1] = K, unused by the reference forward
    const float* Wq = (const float*)d_in[2];
    const float* bq = (const float*)d_in[3];
    const float* Wo = (const float*)d_in[4];
    const float* bo = (const float*)d_in[5];
    const float* g0 = (const float*)d_in[6];
    const float* b0 = (const float*)d_in[7];
    const float* g1 = (const float*)d_in[8];
    const float* b1 = (const float*)d_in[9];
    float* out = (float*)d_out;

    const int SMEM_AV = 9216 * 5 * 2;  // 92160 B
    cudaFuncSetAttribute(sink_av_kernel,
                         cudaFuncAttributeMaxDynamicSharedMemorySize, SMEM_AV);

    dim3 ggrid(4, 64);    // N/128, M/128
    dim3 sgrid(36, 64);   // triangular tile pairs, bh
    dim3 agrid(8, 64);    // row-blocks, bh

    cvt_kernel<<<2304, 256>>>(Q, Wq, Wo);
    gemm512h<0><<<ggrid, 256>>>(bq);
    sym_lse<0><<<sgrid, 256>>>();
    sym_lse<1><<<sgrid, 256>>>();
    qv_kernel<<<2048, 256>>>();
    sink_av_kernel<<<agrid, 256, SMEM_AV>>>();
    ln_kernel<<<8192, 128>>>(g0, b0, nullptr, 0);
    gemm512h<1><<<ggrid, 256>>>(bo);
    ln_kernel<<<8192, 128>>>(g1, b1, out, 1);
}

// round 17
// speedup vs baseline: 1.0351x; 1.0351x over previous
#include <cuda_runtime.h>
#include <cuda_fp16.h>
#include <math.h>
#include <stdint.h>

// Problem constants: B=8, n=1024, dQ=dV=512, H=8, d=64, HB=64
#define NSEQ   1024
#define DHEAD  64
#define DVTOT  512
#define NBATCH 8
#define NHB    64

#define SSCALE 0.044194173824159216f   // 1/sqrt(512)
#define LOG2E  1.4426950408889634f
#define SS2    (SSCALE * LOG2E)        // exp(s*SSCALE) = ex2(s*SS2)
#define SQS    0.2525048957f           // sqrt(SS2); Q stored as Q*SQS
#define CINV   (1.0f / SQS)            // undo one SQS factor in AV output
#define LOGMU  (-6.9314615657f)        // log(1/1024 + 1e-8)
#define MUVAL  (0.0009765725f)         // 1/1024 + 1e-8

// Scratch (device globals; no allocation allowed)
__device__ float  g_Qh  [NHB * NSEQ * DHEAD];   // head-major Q_ fp32 (residual)
__device__ __half g_Qh16[NHB * NSEQ * DHEAD];   // head-major Q_ * SQS fp16
__device__ float  g_Oh [NBATCH * NSEQ * DVTOT]; // O_ in merged (b,i,512) layout
__device__ float  g_X  [NBATCH * NSEQ * DVTOT];
__device__ __half g_X16[NBATCH * NSEQ * DVTOT];
__device__ float  g_T  [NBATCH * NSEQ * DVTOT];
__device__ __half g_A16[NBATCH * NSEQ * DVTOT]; // fp16 Q input
__device__ __half g_W16q[DVTOT * DVTOT];
__device__ __half g_W16o[DVTOT * DVTOT];
// partial sums: g_part (pass 0, row/col sums of P) ; g_part2 (pass 1, for v)
__device__ float  g_part [NHB * 8 * NSEQ];
__device__ float  g_part2[NHB * 8 * NSEQ];

// ---------------------------------------------------------------------------
// helpers
// ---------------------------------------------------------------------------
__device__ __forceinline__ void mma16h(float* c, const unsigned* a, const unsigned* b) {
    asm volatile(
        "mma.sync.aligned.m16n8k16.row.col.f32.f16.f16.f32 "
        "{%0,%1,%2,%3},{%4,%5,%6,%7},{%8,%9},{%0,%1,%2,%3};\n"
        : "+f"(c[0]), "+f"(c[1]), "+f"(c[2]), "+f"(c[3])
        : "r"(a[0]), "r"(a[1]), "r"(a[2]), "r"(a[3]), "r"(b[0]), "r"(b[1]));
}
__device__ __forceinline__ unsigned smaddr(const void* p) {
    return (unsigned)__cvta_generic_to_shared(p);
}
__device__ __forceinline__ void ldm_x4(unsigned* r, unsigned a) {
    asm volatile("ldmatrix.sync.aligned.m8n8.x4.shared.b16 {%0,%1,%2,%3},[%4];"
                 : "=r"(r[0]), "=r"(r[1]), "=r"(r[2]), "=r"(r[3]) : "r"(a));
}
__device__ __forceinline__ void ldm_x4t(unsigned* r, unsigned a) {
    asm volatile("ldmatrix.sync.aligned.m8n8.x4.trans.shared.b16 {%0,%1,%2,%3},[%4];"
                 : "=r"(r[0]), "=r"(r[1]), "=r"(r[2]), "=r"(r[3]) : "r"(a));
}
__device__ __forceinline__ unsigned fh2(float a, float b) {
    __half2 h = __floats2half2_rn(a, b);
    return *(unsigned*)&h;
}
__device__ __forceinline__ unsigned hadd2u(unsigned a, unsigned b) {
    __half2 r = __hadd2(*(const __half2*)&a, *(const __half2*)&b);
    return *(unsigned*)&r;
}
__device__ __forceinline__ float ex2(float x) {
    float r;
    asm("ex2.approx.ftz.f32 %0, %1;" : "=f"(r) : "f"(x));
    return r;
}
__device__ __forceinline__ unsigned h2ex2(unsigned x) {
    unsigned r;
    asm("ex2.approx.f16x2 %0, %1;" : "=r"(r) : "r"(x));
    return r;
}
__device__ __forceinline__ void cpa16(unsigned s, const void* g) {
    asm volatile("cp.async.ca.shared.global [%0], [%1], 16;" :: "r"(s), "l"(g) : "memory");
}
__device__ __forceinline__ void cpa_commit() {
    asm volatile("cp.async.commit_group;" ::: "memory");
}
template <int N>
__device__ __forceinline__ void cpa_wait() {
    asm volatile("cp.async.wait_group %0;" :: "n"(N) : "memory");
}

// ---------------------------------------------------------------------------
// fp32 -> fp16 conversion for GEMM operands (Q, Wq, Wo). One launch.
// ---------------------------------------------------------------------------
__global__ void __launch_bounds__(256) cvt_kernel(const float* __restrict__ Q,
                                                  const float* __restrict__ Wq,
                                                  const float* __restrict__ Wo) {
    size_t t = ((size_t)blockIdx.x * 256 + threadIdx.x) * 8;
    const float* src;
    __half* dst;
    size_t off;
    if (t < 4194304) { src = Q;  dst = g_A16;  off = t; }
    else if (t < 4456448) { src = Wq; dst = g_W16q; off = t - 4194304; }
    else { src = Wo; dst = g_W16o; off = t - 4456448; }
    float4 a = *(const float4*)(src + off);
    float4 b = *(const float4*)(src + off + 4);
    uint4 p;
    p.x = fh2(a.x, a.y); p.y = fh2(a.z, a.w);
    p.z = fh2(b.x, b.y); p.w = fh2(b.z, b.w);
    *(uint4*)(dst + off) = p;
}

// ---------------------------------------------------------------------------
// Symmetric-tile LSE pass. 3 CTAs/SM. Both operands from the sqrt-scaled
// copy -> S arrives pre-scaled by SS2, zero prescale instructions.
// MODE 0: partials of rowsum/colsum of P -> g_part
// MODE 1: e^u from g_part; weighted partials for v -> g_part2
// ---------------------------------------------------------------------------
template <int MODE>
__global__ void __launch_bounds__(256, 3) sym_lse() {
    __shared__ __align__(16) __half Qi[128 * 72];
    __shared__ __align__(16) __half Qj[128 * 72];
    __shared__ float csh[4][128];
    __shared__ float ps[256];
    __shared__ float eua[128], eub[128];

    const int bh = blockIdx.y;
    int a = 0, tt = blockIdx.x;
    while (tt >= 8 - a) { tt -= 8 - a; a++; }
    const int b = a + tt;

    const int tid = threadIdx.x, lane = tid & 31, w = tid >> 5;
    const int mw = w & 3, w2 = w >> 2;
    const int wm = mw * 32, wn = w2 * 64;
    const __half* Qb = g_Qh16 + (size_t)bh * (NSEQ * DHEAD);

#pragma unroll
    for (int r = 0; r < 4; r++) {
        int idx = tid + r * 256;
        int row = idx >> 3, q = (idx & 7) * 8;
        cpa16(smaddr(Qi + row * 72 + q), Qb + (size_t)(a * 128 + row) * DHEAD + q);
        cpa16(smaddr(Qj + row * 72 + q), Qb + (size_t)(b * 128 + row) * DHEAD + q);
    }
    if (MODE == 1 && tid < 128) {
        float sa_ = 0.f, sb_ = 0.f;
#pragma unroll
        for (int k = 0; k < 8; k++) {
            sa_ += g_part[((size_t)bh * 8 + k) * NSEQ + a * 128 + tid];
            sb_ += g_part[((size_t)bh * 8 + k) * NSEQ + b * 128 + tid];
        }
        eua[tid] = MUVAL / sa_;
        eub[tid] = MUVAL / sb_;
    }
    cpa_commit();
    cpa_wait<0>();
    __syncthreads();

    float eu4[2][2];
    if (MODE == 1) {
#pragma unroll
        for (int mt = 0; mt < 2; mt++)
#pragma unroll
            for (int h = 0; h < 2; h++)
                eu4[mt][h] = eua[wm + mt * 16 + (lane >> 2) + h * 8];
    }

    float ls[2][2] = {{0.f, 0.f}, {0.f, 0.f}};

#pragma unroll
    for (int nh = 0; nh < 2; nh++) {
        const int wnh = wn + nh * 32;

        float sa[2][4][4];
#pragma unroll
        for (int x = 0; x < 2; x++)
#pragma unroll
            for (int y = 0; y < 4; y++)
#pragma unroll
                for (int z = 0; z < 4; z++) sa[x][y][z] = 0.f;

#pragma unroll
        for (int kk = 0; kk < 4; kk++) {
            unsigned af0[4], af1[4];
            {
                int col = kk * 16 + (lane >> 4) * 8;
                ldm_x4(af0, smaddr(Qi + (wm + (lane & 15)) * 72 + col));
                ldm_x4(af1, smaddr(Qi + (wm + 16 + (lane & 15)) * 72 + col));
            }
#pragma unroll
            for (int nb = 0; nb < 2; nb++) {
                unsigned bq[4];
                ldm_x4(bq, smaddr(Qj + (wnh + nb * 16 + ((lane >> 4) & 1) * 8 + (lane & 7)) * 72 +
                                  kk * 16 + ((lane >> 3) & 1) * 8));
                mma16h(sa[0][2 * nb], af0, bq);
                mma16h(sa[1][2 * nb], af1, bq);
                mma16h(sa[0][2 * nb + 1], af0, bq + 2);
                mma16h(sa[1][2 * nb + 1], af1, bq + 2);
            }
        }

        float cp[4][2];
#pragma unroll
        for (int nt = 0; nt < 4; nt++) { cp[nt][0] = 0.f; cp[nt][1] = 0.f; }

#pragma unroll
        for (int mt = 0; mt < 2; mt++)
#pragma unroll
            for (int nt = 0; nt < 4; nt++) {
                int colb = wnh + nt * 8 + 2 * (lane & 3);
#pragma unroll
                for (int rg = 0; rg < 4; rg++) {
                    float e = ex2(sa[mt][nt][rg]);   // SS2 baked via sqrt-scaled Q
                    int h = rg >> 1, d = rg & 1;
                    if (MODE == 0) {
                        ls[mt][h] += e;
                        cp[nt][d] += e;
                    } else {
                        ls[mt][h] += eub[colb + d] * e;
                        cp[nt][d] += eu4[mt][h] * e;
                    }
                }
            }

#pragma unroll
        for (int nt = 0; nt < 4; nt++)
#pragma unroll
            for (int d = 0; d < 2; d++) {
                float v = cp[nt][d];
                v += __shfl_xor_sync(0xffffffffu, v, 4);
                v += __shfl_xor_sync(0xffffffffu, v, 8);
                v += __shfl_xor_sync(0xffffffffu, v, 16);
                cp[nt][d] = v;
            }
        if (lane < 4) {
#pragma unroll
            for (int nt = 0; nt < 4; nt++) {
                csh[mw][wnh + nt * 8 + 2 * lane + 0] = cp[nt][0];
                csh[mw][wnh + nt * 8 + 2 * lane + 1] = cp[nt][1];
            }
        }
    }

#pragma unroll
    for (int mt = 0; mt < 2; mt++)
#pragma unroll
        for (int h = 0; h < 2; h++) {
            float v = ls[mt][h];
            v += __shfl_xor_sync(0xffffffffu, v, 1);
            v += __shfl_xor_sync(0xffffffffu, v, 2);
            if ((lane & 3) == 0)
                ps[w2 * 128 + wm + mt * 16 + (lane >> 2) + h * 8] = v;
        }
    __syncthreads();

    float* dst = (MODE == 0) ? g_part : g_part2;
    if (tid < 128) {
        if (MODE == 0 || a != b) {
            float rs = ps[tid] + ps[128 + tid];
            dst[((size_t)bh * 8 + b) * NSEQ + a * 128 + tid] = rs;
        }
        if (MODE == 1 || a != b) {
            float cs = csh[0][tid] + csh[1][tid] + csh[2][tid] + csh[3][tid];
            dst[((size_t)bh * 8 + a) * NSEQ + b * 128 + tid] = cs;
        }
    }
}

// ---------------------------------------------------------------------------
// Pass C: O_ = Q_ + (1024 e^{u} e^{v} 2^{S*SS2}) @ Q_. Single sqrt-scaled Q
// array feeds S-A, S-B and V; the leftover SQS factor on V is undone by CINV
// in the epilogue FFMA. u fp32; v fp16; ex2.f16x2; 2 CTAs/SM.
// ---------------------------------------------------------------------------
__global__ void __launch_bounds__(256, 2) sink_av_kernel() {
    extern __shared__ __align__(16) char smraw[];
    __half* Qi = (__half*)smraw;                 // 128*72
    __half* QjA = Qi + 9216;                     // 128*72 (buf 0)
    __half* QjB = QjA + 9216;                    // 128*72 (buf 1)
    float* vb = (float*)(QjB + 9216);            // 2 x 128 (log2 units)

    const int bh = blockIdx.y;
    const int i0 = blockIdx.x * 128;
    const int tid = threadIdx.x, lane = tid & 31, w = tid >> 5;
    const int wm = w * 16;
    const __half* Qb = g_Qh16 + (size_t)bh * (NSEQ * DHEAD);
    const float* Qf32 = g_Qh + (size_t)bh * (NSEQ * DHEAD);
    __half* Qbuf[2] = { QjA, QjB };
    const int bb = bh & 7, hh2 = bh >> 3;        // batch, head

#pragma unroll
    for (int r = 0; r < 4; r++) {
        int idx = tid + r * 256;
        int row = idx >> 3, q = (idx & 7) * 8;
        cpa16(smaddr(Qi + row * 72 + q), Qb + (size_t)(i0 + row) * DHEAD + q);
        cpa16(smaddr(QjA + row * 72 + q), Qb + (size_t)row * DHEAD + q);
    }
    if (tid < 128) {
        float s = 0.f;
#pragma unroll
        for (int k = 0; k < 8; k++)
            s += g_part2[((size_t)bh * 8 + k) * NSEQ + tid];
        vb[tid] = (LOGMU - __logf(s)) * LOG2E;
    }
    cpa_commit();

    float r0s = 0.f, r1s = 0.f;
#pragma unroll
    for (int k = 0; k < 8; k++) {
        r0s += g_part[((size_t)bh * 8 + k) * NSEQ + i0 + wm + (lane >> 2)];
        r1s += g_part[((size_t)bh * 8 + k) * NSEQ + i0 + wm + (lane >> 2) + 8];
    }
    const float u0 = (LOGMU - __logf(r0s)) * LOG2E + 10.f;
    const float u1 = (LOGMU - __logf(r1s)) * LOG2E + 10.f;
    cpa_wait<0>();
    __syncthreads();

    unsigned af[4][4];
#pragma unroll
    for (int kk = 0; kk < 4; kk++)
        ldm_x4(af[kk], smaddr(Qi + (wm + (lane & 15)) * 72 + kk * 16 + (lane >> 4) * 8));

    float oa[8][4];
#pragma unroll
    for (int y = 0; y < 8; y++)
#pragma unroll
        for (int z = 0; z < 4; z++) oa[y][z] = 0.f;

    for (int jt = 0; jt < 8; jt++) {
        __syncthreads();
        if (jt < 7) {
            int j0 = (jt + 1) * 128, buf = (jt + 1) & 1;
#pragma unroll
            for (int r = 0; r < 4; r++) {
                int idx = tid + r * 256;
                int row = idx >> 3, q = (idx & 7) * 8;
                cpa16(smaddr(Qbuf[buf] + row * 72 + q),
                      Qb + (size_t)(j0 + row) * DHEAD + q);
            }
            if (tid < 128) {
                float s = 0.f;
#pragma unroll
                for (int k = 0; k < 8; k++)
                    s += g_part2[((size_t)bh * 8 + k) * NSEQ + j0 + tid];
                vb[buf * 128 + tid] = (LOGMU - __logf(s)) * LOG2E;
            }
            cpa_commit();
            cpa_wait<1>();
        } else {
            cpa_wait<0>();
        }
        __syncthreads();

        const __half* Qc = Qbuf[jt & 1];
        const float* vv = vb + (jt & 1) * 128;

#pragma unroll
        for (int h = 0; h < 2; h++) {
            const int jb = h * 64;
            float sa[8][4];
#pragma unroll
            for (int y = 0; y < 8; y++)
#pragma unroll
                for (int z = 0; z < 4; z++) sa[y][z] = 0.f;

#pragma unroll
            for (int kk = 0; kk < 4; kk++) {
#pragma unroll
                for (int nb = 0; nb < 4; nb++) {
                    unsigned bq[4];
                    ldm_x4(bq, smaddr(Qc + (jb + nb * 16 + ((lane >> 4) & 1) * 8 + (lane & 7)) * 72 +
                                      kk * 16 + ((lane >> 3) & 1) * 8));
                    mma16h(sa[2 * nb], af[kk], bq);
                    mma16h(sa[2 * nb + 1], af[kk], bq + 2);
                }
            }

            unsigned ak[4][4];
#pragma unroll
            for (int s2 = 0; s2 < 4; s2++) {
                const float* s0 = sa[2 * s2];
                const float* s1 = sa[2 * s2 + 1];
                int c0 = jb + s2 * 16 + 2 * (lane & 3);
                int c8 = c0 + 8;
                float2 v0p = *(const float2*)(vv + c0);
                float2 v8p = *(const float2*)(vv + c8);
                unsigned vh0 = fh2(v0p.x, v0p.y);
                unsigned vh8 = fh2(v8p.x, v8p.y);
                unsigned p00 = fh2(s0[0] + u0, s0[1] + u0);   // S pre-scaled
                unsigned p01 = fh2(s0[2] + u1, s0[3] + u1);
                unsigned p80 = fh2(s1[0] + u0, s1[1] + u0);
                unsigned p81 = fh2(s1[2] + u1, s1[3] + u1);
                ak[s2][0] = h2ex2(hadd2u(p00, vh0));
                ak[s2][1] = h2ex2(hadd2u(p01, vh0));
                ak[s2][2] = h2ex2(hadd2u(p80, vh8));
                ak[s2][3] = h2ex2(hadd2u(p81, vh8));
            }

#pragma unroll
            for (int s2 = 0; s2 < 4; s2++) {
#pragma unroll
                for (int nb = 0; nb < 4; nb++) {
                    unsigned bq[4];
                    ldm_x4t(bq, smaddr(Qc + (jb + s2 * 16 + (lane & 15)) * 72 +
                                       nb * 16 + ((lane >> 4) & 1) * 8));
                    mma16h(oa[2 * nb], ak[s2], bq);
                    mma16h(oa[2 * nb + 1], ak[s2], bq + 2);
                }
            }
        }
    }

    // epilogue: O_ = Q_ + CINV * oa (undo SQS on V), merged layout, float2
#pragma unroll
    for (int nt = 0; nt < 8; nt++) {
        int ri = i0 + wm + (lane >> 2);
        int col = nt * 8 + 2 * (lane & 3);
        int gcol = hh2 * 64 + col;
        float2 q0 = *(const float2*)(Qf32 + (size_t)ri * DHEAD + col);
        float2 o0 = { oa[nt][0] * CINV + q0.x, oa[nt][1] * CINV + q0.y };
        *(float2*)(g_Oh + ((size_t)(bb * NSEQ + ri) * DVTOT) + gcol) = o0;
        int ri8 = ri + 8;
        float2 q1 = *(const float2*)(Qf32 + (size_t)ri8 * DHEAD + col);
        float2 o1 = { oa[nt][2] * CINV + q1.x, oa[nt][3] * CINV + q1.y };
        *(float2*)(g_Oh + ((size_t)(bb * NSEQ + ri8) * DVTOT) + gcol) = o1;
    }
}

// ---------------------------------------------------------------------------
// fp16 GEMM (BM=128 BN=128 BK=64, 2 CTAs/SM, grid 4x64)
// MODE 0: scatter head-major into g_Qh (fp32) + g_Qh16 (*SQS)
// MODE 1: A = g_X16; g_T = g_X + relu(C + bias)
// ---------------------------------------------------------------------------
template <int MODE>
__global__ void __launch_bounds__(256, 2) gemm512h(const float* __restrict__ bias) {
    __shared__ __align__(16) __half As[2][128 * 72];
    __shared__ __align__(16) __half Bs[2][128 * 72];
    const __half* A16 = MODE ? g_X16 : g_A16;
    const __half* W16 = MODE ? g_W16o : g_W16q;

    const int m0 = blockIdx.y * 128, n0 = blockIdx.x * 128;
    const int tid = threadIdx.x, lane = tid & 31, w = tid >> 5;
    const int wm = (w & 3) * 32, wn = (w >> 2) * 64;

    float acc[2][8][4];
#pragma unroll
    for (int x = 0; x < 2; x++)
#pragma unroll
        for (int y = 0; y < 8; y++)
#pragma unroll
            for (int z = 0; z < 4; z++) acc[x][y][z] = 0.f;

#pragma unroll
    for (int c = 0; c < 4; c++) {
        int idx = tid + c * 256;
        int row = idx >> 3, ch = (idx & 7) * 8;
        cpa16(smaddr(&As[0][row * 72 + ch]), A16 + (size_t)(m0 + row) * 512 + ch);
        cpa16(smaddr(&Bs[0][row * 72 + ch]), W16 + (size_t)(n0 + row) * 512 + ch);
    }
    cpa_commit();

    for (int kt = 0; kt < 8; kt++) {
        __syncthreads();
        if (kt < 7) {
            int s = (kt + 1) & 1, k0 = (kt + 1) * 64;
#pragma unroll
            for (int c = 0; c < 4; c++) {
                int idx = tid + c * 256;
                int row = idx >> 3, ch = (idx & 7) * 8;
                cpa16(smaddr(&As[s][row * 72 + ch]), A16 + (size_t)(m0 + row) * 512 + k0 + ch);
                cpa16(smaddr(&Bs[s][row * 72 + ch]), W16 + (size_t)(n0 + row) * 512 + k0 + ch);
            }
            cpa_commit();
            cpa_wait<1>();
        } else {
            cpa_wait<0>();
        }
        __syncthreads();

        const __half* as = As[kt & 1];
        const __half* bs = Bs[kt & 1];
#pragma unroll
        for (int kk = 0; kk < 4; kk++) {
            unsigned af[2][4];
#pragma unroll
            for (int mt = 0; mt < 2; mt++)
                ldm_x4(af[mt], smaddr(as + (wm + mt * 16 + (lane & 15)) * 72 +
                                      kk * 16 + (lane >> 4) * 8));
#pragma unroll
            for (int nb = 0; nb < 4; nb++) {
                unsigned bq[4];
                ldm_x4(bq, smaddr(bs + (wn + nb * 16 + ((lane >> 4) & 1) * 8 + (lane & 7)) * 72 +
                                  kk * 16 + ((lane >> 3) & 1) * 8));
                mma16h(acc[0][2 * nb], af[0], bq);
                mma16h(acc[1][2 * nb], af[1], bq);
                mma16h(acc[0][2 * nb + 1], af[0], bq + 2);
                mma16h(acc[1][2 * nb + 1], af[1], bq + 2);
            }
        }
    }

#pragma unroll
    for (int mt = 0; mt < 2; mt++)
#pragma unroll
        for (int nt = 0; nt < 8; nt++) {
            int row = m0 + wm + mt * 16 + (lane >> 2);
            int col = n0 + wn + nt * 8 + 2 * (lane & 3);
            float b0 = bias[col], b1 = bias[col + 1];
#pragma unroll
            for (int hh = 0; hh < 2; hh++) {
                int rr = row + hh * 8;
                float v0 = acc[mt][nt][2 * hh] + b0;
                float v1 = acc[mt][nt][2 * hh + 1] + b1;
                if (MODE == 0) {
                    int b = rr >> 10, i = rr & 1023;
                    int h = col >> 6, dc = col & 63;
                    size_t idx = ((size_t)((h << 3) + b) * NSEQ + i) * DHEAD + dc;
                    *(float2*)(g_Qh + idx) = make_float2(v0, v1);
                    *(unsigned*)((__half*)g_Qh16 + idx) = fh2(v0 * SQS, v1 * SQS);
                } else {
                    float2 x = *(const float2*)(g_X + (size_t)rr * 512 + col);
                    float2 t = { fmaxf(v0, 0.f) + x.x, fmaxf(v1, 0.f) + x.y };
                    *(float2*)(g_T + (size_t)rr * 512 + col) = t;
                }
            }
        }
}

// ---------------------------------------------------------------------------
// LayerNorm, vectorized: 128 threads x float4, one row per block.
// ---------------------------------------------------------------------------
__global__ void __launch_bounds__(128) ln_kernel(const float* __restrict__ gg,
                                                 const float* __restrict__ bb,
                                                 float* __restrict__ out, int mode) {
    const int m = blockIdx.x, t = threadIdx.x;
    const float* src = (mode == 0) ? g_Oh : g_T;
    float4 v = *(const float4*)(src + (size_t)m * 512 + t * 4);
    float s = v.x + v.y + v.z + v.w;
    float q = v.x * v.x + v.y * v.y + v.z * v.z + v.w * v.w;
#pragma unroll
    for (int off = 16; off; off >>= 1) {
        s += __shfl_xor_sync(0xffffffffu, s, off);
        q += __shfl_xor_sync(0xffffffffu, q, off);
    }
    __shared__ float ss[4], sq[4];
    int wr = t >> 5, lane = t & 31;
    if (!lane) { ss[wr] = s; sq[wr] = q; }
    __syncthreads();
    float S = ss[0] + ss[1] + ss[2] + ss[3];
    float Q2 = sq[0] + sq[1] + sq[2] + sq[3];
    float mean = S * (1.f / 512.f);
    float var = Q2 * (1.f / 512.f) - mean * mean;
    float rstd = rsqrtf(var + 1e-5f);
    float4 G = *(const float4*)(gg + t * 4);
    float4 Bv = *(const float4*)(bb + t * 4);
    float4 y;
    y.x = (v.x - mean) * rstd * G.x + Bv.x;
    y.y = (v.y - mean) * rstd * G.y + Bv.y;
    y.z = (v.z - mean) * rstd * G.z + Bv.z;
    y.w = (v.w - mean) * rstd * G.w + Bv.w;
    if (mode == 0) {
        *(float4*)(g_X + (size_t)m * 512 + t * 4) = y;
        uint2 hp;
        hp.x = fh2(y.x, y.y);
        hp.y = fh2(y.z, y.w);
        *(uint2*)(g_X16 + (size_t)m * 512 + t * 4) = hp;
    } else {
        *(float4*)(out + (size_t)m * 512 + t * 4) = y;
    }
}

// ---------------------------------------------------------------------------
extern "C" void kernel_launch(void* const* d_in, const int* in_sizes, int n_in,
                              void* d_out, int out_size) {
    (void)in_sizes; (void)n_in; (void)out_size;
    const float* Q  = (const float*)d_in[0];
    // d_in[1] = K, unused by the reference forward
    const float* Wq = (const float*)d_in[2];
    const float* bq = (const float*)d_in[3];
    const float* Wo = (const float*)d_in[4];
    const float* bo = (const float*)d_in[5];
    const float* g0 = (const float*)d_in[6];
    const float* b0 = (const float*)d_in[7];
    const float* g1 = (const float*)d_in[8];
    const float* b1 = (const float*)d_in[9];
    float* out = (float*)d_out;

    const int SMEM_AV = 9216 * 3 * 2 + 256 * 4;  // 56320 B
    cudaFuncSetAttribute(sink_av_kernel,
                         cudaFuncAttributeMaxDynamicSharedMemorySize, SMEM_AV);

    dim3 ggrid(4, 64);    // N/128, M/128
    dim3 sgrid(36, 64);   // triangular tile pairs, bh
    dim3 agrid(8, 64);    // row-blocks, bh

    cvt_kernel<<<2304, 256>>>(Q, Wq, Wo);
    gemm512h<0><<<ggrid, 256>>>(bq);
    sym_lse<0><<<sgrid, 256>>>();
    sym_lse<1><<<sgrid, 256>>>();
    sink_av_kernel<<<agrid, 256, SMEM_AV>>>();
    ln_kernel<<<8192, 128>>>(g0, b0, nullptr, 0);
    gemm512h<1><<<ggrid, 256>>>(bo);
    ln_kernel<<<8192, 128>>>(g1, b1, out, 1);
}